// round 11
// baseline (speedup 1.0000x reference)
#include <cuda_runtime.h>

#define N_NODES   200000
#define N_EDGES   3200000
#define HIDDEN    64
#define N_GRAPHS  4096
#define N_CLASSES 7

// ---------------- scratch (static device globals; no runtime allocation) ----
__device__ __align__(16) float g_A[(size_t)N_NODES * HIDDEN];  // xw (gather src)
__device__ __align__(16) float g_B[(size_t)N_NODES * HIDDEN];  // h accum (scatter dst)
__device__ float g_dinv[N_NODES];                 // degree, then rsqrt(degree)
__device__ float g_sums[N_GRAPHS * HIDDEN];
__device__ float g_cnt[N_GRAPHS];

// ---------------- init: deg=1 (self-loop), zero pool accumulators -----------
__global__ void k_init() {
    int i = blockIdx.x * blockDim.x + threadIdx.x;
    if (i < N_NODES) g_dinv[i] = 1.0f;
    if (i < N_GRAPHS * HIDDEN) g_sums[i] = 0.0f;
    if (i < N_GRAPHS) g_cnt[i] = 0.0f;
}

// ---------------- degree accumulation over edges ----------------------------
__global__ void k_deg(const int* __restrict__ dst) {
    int e = blockIdx.x * blockDim.x + threadIdx.x;
    if (e < N_EDGES) atomicAdd(&g_dinv[dst[e]], 1.0f);
}

__global__ void k_rsqrt() {
    int i = blockIdx.x * blockDim.x + threadIdx.x;
    if (i < N_NODES) g_dinv[i] = rsqrtf(g_dinv[i]);
}

// ---------------- layer 1 dense: x[N,2] @ W1[2,64]; init B with self-loop ---
__global__ void k_dense1(const float* __restrict__ x, const float* __restrict__ W1) {
    int idx = blockIdx.x * blockDim.x + threadIdx.x;     // N*64 threads
    if (idx >= N_NODES * HIDDEN) return;
    int i = idx >> 6;
    int j = idx & 63;
    float v = x[2 * i] * W1[j] + x[2 * i + 1] * W1[64 + j];
    g_A[idx] = v;
    float di = g_dinv[i];
    g_B[idx] = di * di * v;                              // self-loop term
}

// ---------------- layers 2/3 dense: relu(B + b_prev) @ W[64,64] -------------
// blockDim = 512 (64 features x 8 nodes). Reads B row fully before writing it.
__global__ void k_dense(const float* __restrict__ W, const float* __restrict__ bprev) {
    __shared__ float Ws[64 * 64];
    __shared__ float in_s[8][64];
    int tx = threadIdx.x & 63;
    int ty = threadIdx.x >> 6;
    for (int idx = threadIdx.x; idx < 64 * 64; idx += 512) Ws[idx] = W[idx];
    int node = blockIdx.x * 8 + ty;
    in_s[ty][tx] = fmaxf(g_B[node * 64 + tx] + bprev[tx], 0.0f);
    __syncthreads();
    float acc = 0.0f;
#pragma unroll
    for (int k = 0; k < 64; k++) acc += in_s[ty][k] * Ws[k * 64 + tx];
    g_A[node * 64 + tx] = acc;
    float di = g_dinv[node];
    g_B[node * 64 + tx] = di * di * acc;                 // self-loop init
}

// ---------------- edge scatter: B[dst] += dinv[s]*dinv[d] * A[src] ----------
// 16 threads per edge; each handles one float4 (gather 256B/edge contiguous,
// scatter via red.global.add.v4.f32 -> 16 vector reductions per edge).
__global__ void k_scatter(const int* __restrict__ src,
                          const int* __restrict__ dst) {
    unsigned gid = blockIdx.x * blockDim.x + threadIdx.x;
    unsigned e = gid >> 4;
    if (e >= N_EDGES) return;
    int c = gid & 15;
    int s = src[e];
    int d = dst[e];
    float w = g_dinv[s] * g_dinv[d];
    const float4* a4 = reinterpret_cast<const float4*>(g_A);
    float4 v = a4[s * 16 + c];
    float4* p = reinterpret_cast<float4*>(g_B) + (d * 16 + c);
    asm volatile("red.global.add.v4.f32 [%0], {%1, %2, %3, %4};"
                 :: "l"(p), "f"(w * v.x), "f"(w * v.y), "f"(w * v.z), "f"(w * v.w)
                 : "memory");
}

// ---------------- global mean pool (bias+relu of layer 3 fused) -------------
__global__ void k_pool(const int* __restrict__ batch,
                       const float* __restrict__ b3) {
    int idx = blockIdx.x * blockDim.x + threadIdx.x;     // N*64 threads
    if (idx >= N_NODES * HIDDEN) return;
    int i = idx >> 6;
    int j = idx & 63;
    int g = batch[i];
    float v = fmaxf(g_B[idx] + b3[j], 0.0f);
    atomicAdd(&g_sums[g * 64 + j], v);
    if (j == 0) atomicAdd(&g_cnt[g], 1.0f);
}

// ---------------- MLP head: one block (64 thr) per graph --------------------
__global__ void k_mlp(const float* __restrict__ Wf1, const float* __restrict__ bf1,
                      const float* __restrict__ Wf2, const float* __restrict__ bf2,
                      float* __restrict__ out) {
    __shared__ float p[64];
    __shared__ float hid[64];
    int g = blockIdx.x;
    int tx = threadIdx.x;
    float cnt = fmaxf(g_cnt[g], 1.0f);
    p[tx] = g_sums[g * 64 + tx] / cnt;
    __syncthreads();
    float a = bf1[tx];
#pragma unroll
    for (int k = 0; k < 64; k++) a += p[k] * Wf1[k * 64 + tx];
    hid[tx] = fmaxf(a, 0.0f);
    __syncthreads();
    if (tx < N_CLASSES) {
        float o = bf2[tx];
#pragma unroll
        for (int k = 0; k < 64; k++) o += hid[k] * Wf2[k * N_CLASSES + tx];
        out[g * N_CLASSES + tx] = o;
    }
}

// ---------------- launch ----------------------------------------------------
extern "C" void kernel_launch(void* const* d_in, const int* in_sizes, int n_in,
                              void* d_out, int out_size) {
    const float* x     = (const float*)d_in[0];
    const int*   ei    = (const int*)d_in[1];     // [2, E] int32 (JAX x64 disabled)
    const int*   batch = (const int*)d_in[2];     // [N] int32
    const float* W1  = (const float*)d_in[3];
    const float* b1  = (const float*)d_in[4];
    const float* W2  = (const float*)d_in[5];
    const float* b2  = (const float*)d_in[6];
    const float* W3  = (const float*)d_in[7];
    const float* b3  = (const float*)d_in[8];
    const float* Wf1 = (const float*)d_in[9];
    const float* bf1 = (const float*)d_in[10];
    const float* Wf2 = (const float*)d_in[11];
    const float* bf2 = (const float*)d_in[12];
    float* out = (float*)d_out;

    const int* src = ei;
    const int* dst = ei + N_EDGES;

    const int elemN = N_NODES * HIDDEN;                 // 12,800,000
    const int gridElem = (elemN + 255) / 256;           // 50,000
    const int gridScat = (N_EDGES * 16) / 256;          // 200,000
    const int gridNode = (N_NODES + 255) / 256;         // 782

    k_init<<<(N_GRAPHS * HIDDEN + 255) / 256, 256>>>();
    k_deg<<<(N_EDGES + 255) / 256, 256>>>(dst);
    k_rsqrt<<<gridNode, 256>>>();

    // layer 1
    k_dense1<<<gridElem, 256>>>(x, W1);
    k_scatter<<<gridScat, 256>>>(src, dst);
    // layer 2 (applies b1+relu to layer-1 output)
    k_dense<<<N_NODES / 8, 512>>>(W2, b1);
    k_scatter<<<gridScat, 256>>>(src, dst);
    // layer 3 (applies b2+relu)
    k_dense<<<N_NODES / 8, 512>>>(W3, b2);
    k_scatter<<<gridScat, 256>>>(src, dst);

    // pool (applies b3+relu) + head
    k_pool<<<gridElem, 256>>>(batch, b3);
    k_mlp<<<N_GRAPHS, 64>>>(Wf1, bf1, Wf2, bf2, out);
}

// round 12
// speedup vs baseline: 1.4948x; 1.4948x over previous
#include <cuda_runtime.h>

#define N_NODES   200000
#define N_EDGES   3200000
#define HIDDEN    64
#define N_GRAPHS  4096
#define N_CLASSES 7

#define SCAN_BLK  1024
#define N_SBLK    ((N_NODES + SCAN_BLK - 1) / SCAN_BLK)   // 196

// ---------------- scratch (static device globals; no runtime allocation) ----
__device__ __align__(16) float g_A[(size_t)N_NODES * HIDDEN];  // xw (gather src)
__device__ __align__(16) float g_B[(size_t)N_NODES * HIDDEN];  // aggregated out
__device__ float g_dinv[N_NODES];
__device__ int   g_count[N_NODES];
__device__ int   g_row[N_NODES + 1];
__device__ int   g_cursor[N_NODES];
__device__ int   g_bsum[N_SBLK];
__device__ int2  g_epack[N_EDGES];        // (src, weight bits) sorted by dst
__device__ float g_sums[N_GRAPHS * HIDDEN];
__device__ float g_cnt[N_GRAPHS];

// ---------------- init: zero degree counts + pool accumulators --------------
__global__ void k_init() {
    int i = blockIdx.x * blockDim.x + threadIdx.x;
    if (i < N_NODES) g_count[i] = 0;
    if (i < N_GRAPHS * HIDDEN) g_sums[i] = 0.0f;
    if (i < N_GRAPHS) g_cnt[i] = 0.0f;
}

// ---------------- degree histogram over dst ---------------------------------
__global__ void k_deg(const int* __restrict__ dst) {
    int e = blockIdx.x * blockDim.x + threadIdx.x;
    if (e < N_EDGES) atomicAdd(&g_count[dst[e]], 1);
}

// ---------------- prefix scan (3 kernels) -----------------------------------
__global__ void k_scan1() {                        // per-block exclusive scan
    __shared__ int sh[SCAN_BLK];
    int t = threadIdx.x;
    int i = blockIdx.x * SCAN_BLK + t;
    int v = (i < N_NODES) ? g_count[i] : 0;
    sh[t] = v;
    __syncthreads();
    for (int off = 1; off < SCAN_BLK; off <<= 1) {
        int x = (t >= off) ? sh[t - off] : 0;
        __syncthreads();
        sh[t] += x;
        __syncthreads();
    }
    if (i < N_NODES) g_row[i] = sh[t] - v;          // exclusive within block
    if (t == SCAN_BLK - 1) g_bsum[blockIdx.x] = sh[t];
}

__global__ void k_scan2() {                        // scan the 196 block sums
    __shared__ int sh[256];
    int t = threadIdx.x;
    int v = (t < N_SBLK) ? g_bsum[t] : 0;
    sh[t] = v;
    __syncthreads();
    for (int off = 1; off < 256; off <<= 1) {
        int x = (t >= off) ? sh[t - off] : 0;
        __syncthreads();
        sh[t] += x;
        __syncthreads();
    }
    if (t < N_SBLK) g_bsum[t] = sh[t] - v;          // exclusive
}

__global__ void k_scan3() {                        // add offsets; dinv; cursor
    int i = blockIdx.x * blockDim.x + threadIdx.x;
    if (i >= N_NODES) return;
    int r = g_row[i] + g_bsum[i / SCAN_BLK];
    g_row[i] = r;
    g_cursor[i] = r;
    g_dinv[i] = rsqrtf((float)(g_count[i] + 1));    // +1 for self-loop
    if (i == 0) g_row[N_NODES] = N_EDGES;
}

// ---------------- fill CSR: pack (src, dinv[s]*dinv[d]) sorted by dst -------
__global__ void k_fill(const int* __restrict__ src, const int* __restrict__ dst) {
    int e = blockIdx.x * blockDim.x + threadIdx.x;
    if (e >= N_EDGES) return;
    int s = src[e];
    int d = dst[e];
    float w = g_dinv[s] * g_dinv[d];
    int pos = atomicAdd(&g_cursor[d], 1);
    g_epack[pos] = make_int2(s, __float_as_int(w));
}

// ---------------- layer 1 dense: x[N,2] @ W1[2,64] (float4-vectorized) ------
__global__ void k_dense1(const float* __restrict__ x, const float* __restrict__ W1) {
    int idx = blockIdx.x * blockDim.x + threadIdx.x;      // N*16 threads
    if (idx >= N_NODES * 16) return;
    int i = idx >> 4;
    int c = idx & 15;
    float x0 = x[2 * i], x1 = x[2 * i + 1];
    float4 wa = *reinterpret_cast<const float4*>(W1 + 4 * c);
    float4 wb = *reinterpret_cast<const float4*>(W1 + 64 + 4 * c);
    float4 v;
    v.x = x0 * wa.x + x1 * wb.x;
    v.y = x0 * wa.y + x1 * wb.y;
    v.z = x0 * wa.z + x1 * wb.z;
    v.w = x0 * wa.w + x1 * wb.w;
    reinterpret_cast<float4*>(g_A)[idx] = v;
}

// ---------------- layers 2/3 dense: relu(B + b_prev) @ W[64,64] -> A --------
__global__ void k_dense(const float* __restrict__ W, const float* __restrict__ bprev) {
    __shared__ float Ws[64 * 64];
    __shared__ float in_s[8][64];
    int tx = threadIdx.x & 63;
    int ty = threadIdx.x >> 6;
    for (int idx = threadIdx.x; idx < 64 * 64; idx += 512) Ws[idx] = W[idx];
    int node = blockIdx.x * 8 + ty;
    in_s[ty][tx] = fmaxf(g_B[node * 64 + tx] + bprev[tx], 0.0f);
    __syncthreads();
    float acc = 0.0f;
#pragma unroll
    for (int k = 0; k < 64; k++) acc += in_s[ty][k] * Ws[k * 64 + tx];
    g_A[node * 64 + tx] = acc;
}

// ---------------- pull aggregation: B[d] = di^2*A[d] + sum w*A[s] -----------
// 16 threads per node (one float4 column each); no atomics, B written once.
__global__ void k_agg() {
    int t = threadIdx.x;
    int node = blockIdx.x * 16 + (t >> 4);
    int c = t & 15;
    const float4* __restrict__ a4 = reinterpret_cast<const float4*>(g_A);
    float di = g_dinv[node];
    float4 self = a4[node * 16 + c];
    float ws = di * di;
    float4 acc = make_float4(ws * self.x, ws * self.y, ws * self.z, ws * self.w);
    int b = g_row[node];
    int e = g_row[node + 1];
    int i = b;
    for (; i + 1 < e; i += 2) {                    // 2-way unroll for MLP
        int2 p0 = g_epack[i];
        int2 p1 = g_epack[i + 1];
        float4 v0 = a4[p0.x * 16 + c];
        float4 v1 = a4[p1.x * 16 + c];
        float w0 = __int_as_float(p0.y);
        float w1 = __int_as_float(p1.y);
        acc.x += w0 * v0.x + w1 * v1.x;
        acc.y += w0 * v0.y + w1 * v1.y;
        acc.z += w0 * v0.z + w1 * v1.z;
        acc.w += w0 * v0.w + w1 * v1.w;
    }
    if (i < e) {
        int2 p = g_epack[i];
        float4 v = a4[p.x * 16 + c];
        float w = __int_as_float(p.y);
        acc.x += w * v.x; acc.y += w * v.y; acc.z += w * v.z; acc.w += w * v.w;
    }
    reinterpret_cast<float4*>(g_B)[node * 16 + c] = acc;
}

// ---------------- pool: run-length compressed atomics (batch is sorted) -----
__global__ void k_pool(const int* __restrict__ batch, const float* __restrict__ b3) {
    int t = threadIdx.x;
    int j = t & 63;
    int base = (blockIdx.x * 4 + (t >> 6)) * 16;    // 16 consecutive nodes
    float bias = b3[j];
    int gcur = batch[base];
    float acc = 0.0f;
    int cnt = 0;
#pragma unroll
    for (int k = 0; k < 16; k++) {
        int node = base + k;
        int g = batch[node];
        if (g != gcur) {
            atomicAdd(&g_sums[gcur * 64 + j], acc);
            if (j == 0) atomicAdd(&g_cnt[gcur], (float)cnt);
            acc = 0.0f; cnt = 0; gcur = g;
        }
        acc += fmaxf(g_B[node * 64 + j] + bias, 0.0f);
        cnt++;
    }
    atomicAdd(&g_sums[gcur * 64 + j], acc);
    if (j == 0) atomicAdd(&g_cnt[gcur], (float)cnt);
}

// ---------------- MLP head: one block (64 thr) per graph --------------------
__global__ void k_mlp(const float* __restrict__ Wf1, const float* __restrict__ bf1,
                      const float* __restrict__ Wf2, const float* __restrict__ bf2,
                      float* __restrict__ out) {
    __shared__ float p[64];
    __shared__ float hid[64];
    int g = blockIdx.x;
    int tx = threadIdx.x;
    float cnt = fmaxf(g_cnt[g], 1.0f);
    p[tx] = g_sums[g * 64 + tx] / cnt;
    __syncthreads();
    float a = bf1[tx];
#pragma unroll
    for (int k = 0; k < 64; k++) a += p[k] * Wf1[k * 64 + tx];
    hid[tx] = fmaxf(a, 0.0f);
    __syncthreads();
    if (tx < N_CLASSES) {
        float o = bf2[tx];
#pragma unroll
        for (int k = 0; k < 64; k++) o += hid[k] * Wf2[k * N_CLASSES + tx];
        out[g * N_CLASSES + tx] = o;
    }
}

// ---------------- launch ----------------------------------------------------
extern "C" void kernel_launch(void* const* d_in, const int* in_sizes, int n_in,
                              void* d_out, int out_size) {
    const float* x     = (const float*)d_in[0];
    const int*   ei    = (const int*)d_in[1];     // [2, E] int32
    const int*   batch = (const int*)d_in[2];     // [N] int32
    const float* W1  = (const float*)d_in[3];
    const float* b1  = (const float*)d_in[4];
    const float* W2  = (const float*)d_in[5];
    const float* b2  = (const float*)d_in[6];
    const float* W3  = (const float*)d_in[7];
    const float* b3  = (const float*)d_in[8];
    const float* Wf1 = (const float*)d_in[9];
    const float* bf1 = (const float*)d_in[10];
    const float* Wf2 = (const float*)d_in[11];
    const float* bf2 = (const float*)d_in[12];
    float* out = (float*)d_out;

    const int* src = ei;
    const int* dst = ei + N_EDGES;

    const int gridEdge = (N_EDGES + 255) / 256;     // 12500
    const int gridNode = (N_NODES + 255) / 256;     // 782
    const int gridAgg  = N_NODES / 16;              // 12500

    // ---- CSR build (once, reused by all 3 layers) ----
    k_init<<<(N_GRAPHS * HIDDEN + 255) / 256, 256>>>();
    k_deg<<<gridEdge, 256>>>(dst);
    k_scan1<<<N_SBLK, SCAN_BLK>>>();
    k_scan2<<<1, 256>>>();
    k_scan3<<<gridNode, 256>>>();
    k_fill<<<gridEdge, 256>>>(src, dst);

    // ---- layer 1 ----
    k_dense1<<<(N_NODES * 16 + 255) / 256, 256>>>(x, W1);
    k_agg<<<gridAgg, 256>>>();
    // ---- layer 2 (applies b1+relu) ----
    k_dense<<<N_NODES / 8, 512>>>(W2, b1);
    k_agg<<<gridAgg, 256>>>();
    // ---- layer 3 (applies b2+relu) ----
    k_dense<<<N_NODES / 8, 512>>>(W3, b2);
    k_agg<<<gridAgg, 256>>>();

    // ---- pool (applies b3+relu) + head ----
    k_pool<<<N_NODES / 64, 256>>>(batch, b3);
    k_mlp<<<N_GRAPHS, 64>>>(Wf1, bf1, Wf2, bf2, out);
}

// round 13
// speedup vs baseline: 1.7872x; 1.1957x over previous
#include <cuda_runtime.h>
#include <cuda_fp16.h>

#define N_NODES   200000
#define N_EDGES   3200000
#define HIDDEN    64
#define N_GRAPHS  4096
#define N_CLASSES 7

#define SCAN_BLK  1024
#define N_SBLK    ((N_NODES + SCAN_BLK - 1) / SCAN_BLK)   // 196

// ---------------- scratch (static device globals; no runtime allocation) ----
__device__ __align__(16) __half g_Ah[(size_t)N_NODES * HIDDEN]; // fp16 features (gather src)
__device__ __align__(16) float  g_B[(size_t)N_NODES * HIDDEN];  // fp32 aggregated out
__device__ float g_dinv[N_NODES];
__device__ int   g_count[N_NODES];
__device__ int   g_row[N_NODES + 1];
__device__ int   g_cursor[N_NODES];
__device__ int   g_bsum[N_SBLK];
__device__ int2  g_epack[N_EDGES];        // (src, weight bits) grouped by dst
__device__ float g_sums[N_GRAPHS * HIDDEN];
__device__ float g_cnt[N_GRAPHS];

// ---------------- init: zero degree counts + pool accumulators --------------
__global__ void k_init() {
    int i = blockIdx.x * blockDim.x + threadIdx.x;
    if (i < N_NODES) g_count[i] = 0;
    if (i < N_GRAPHS * HIDDEN) g_sums[i] = 0.0f;
    if (i < N_GRAPHS) g_cnt[i] = 0.0f;
}

// ---------------- degree histogram over dst ---------------------------------
__global__ void k_deg(const int* __restrict__ dst) {
    int e = blockIdx.x * blockDim.x + threadIdx.x;
    if (e < N_EDGES) atomicAdd(&g_count[dst[e]], 1);
}

// ---------------- prefix scan (3 kernels) -----------------------------------
__global__ void k_scan1() {                        // per-block exclusive scan
    __shared__ int sh[SCAN_BLK];
    int t = threadIdx.x;
    int i = blockIdx.x * SCAN_BLK + t;
    int v = (i < N_NODES) ? g_count[i] : 0;
    sh[t] = v;
    __syncthreads();
    for (int off = 1; off < SCAN_BLK; off <<= 1) {
        int x = (t >= off) ? sh[t - off] : 0;
        __syncthreads();
        sh[t] += x;
        __syncthreads();
    }
    if (i < N_NODES) g_row[i] = sh[t] - v;          // exclusive within block
    if (t == SCAN_BLK - 1) g_bsum[blockIdx.x] = sh[t];
}

__global__ void k_scan2() {                        // scan the 196 block sums
    __shared__ int sh[256];
    int t = threadIdx.x;
    int v = (t < N_SBLK) ? g_bsum[t] : 0;
    sh[t] = v;
    __syncthreads();
    for (int off = 1; off < 256; off <<= 1) {
        int x = (t >= off) ? sh[t - off] : 0;
        __syncthreads();
        sh[t] += x;
        __syncthreads();
    }
    if (t < N_SBLK) g_bsum[t] = sh[t] - v;          // exclusive
}

__global__ void k_scan3() {                        // add offsets; dinv; cursor
    int i = blockIdx.x * blockDim.x + threadIdx.x;
    if (i >= N_NODES) return;
    int r = g_row[i] + g_bsum[i / SCAN_BLK];
    g_row[i] = r;
    g_cursor[i] = r;
    g_dinv[i] = rsqrtf((float)(g_count[i] + 1));    // +1 for self-loop
    if (i == 0) g_row[N_NODES] = N_EDGES;
}

// ---------------- fill CSR: pack (src, dinv[s]*dinv[d]) grouped by dst ------
__global__ void k_fill(const int* __restrict__ src, const int* __restrict__ dst) {
    int e = blockIdx.x * blockDim.x + threadIdx.x;
    if (e >= N_EDGES) return;
    int s = src[e];
    int d = dst[e];
    float w = g_dinv[s] * g_dinv[d];
    int pos = atomicAdd(&g_cursor[d], 1);
    g_epack[pos] = make_int2(s, __float_as_int(w));
}

// ---------------- layer 1 dense: x[N,2] @ W1[2,64] -> fp16 A ----------------
__global__ void k_dense1(const float* __restrict__ x, const float* __restrict__ W1) {
    int idx = blockIdx.x * blockDim.x + threadIdx.x;      // N*16 threads
    if (idx >= N_NODES * 16) return;
    int i = idx >> 4;
    int c = idx & 15;
    float x0 = x[2 * i], x1 = x[2 * i + 1];
    float4 wa = *reinterpret_cast<const float4*>(W1 + 4 * c);
    float4 wb = *reinterpret_cast<const float4*>(W1 + 64 + 4 * c);
    __half2 h0 = __floats2half2_rn(x0 * wa.x + x1 * wb.x, x0 * wa.y + x1 * wb.y);
    __half2 h1 = __floats2half2_rn(x0 * wa.z + x1 * wb.z, x0 * wa.w + x1 * wb.w);
    uint2 pk;
    pk.x = *reinterpret_cast<unsigned*>(&h0);
    pk.y = *reinterpret_cast<unsigned*>(&h1);
    reinterpret_cast<uint2*>(g_Ah)[idx] = pk;             // 8B: 4 halves
}

// ---------------- layers 2/3 dense: relu(B + b_prev) @ W[64,64] -> fp16 A ---
__global__ void k_dense(const float* __restrict__ W, const float* __restrict__ bprev) {
    __shared__ float Ws[64 * 64];
    __shared__ float in_s[8][64];
    int tx = threadIdx.x & 63;
    int ty = threadIdx.x >> 6;
    for (int idx = threadIdx.x; idx < 64 * 64; idx += 512) Ws[idx] = W[idx];
    int node = blockIdx.x * 8 + ty;
    in_s[ty][tx] = fmaxf(g_B[node * 64 + tx] + bprev[tx], 0.0f);
    __syncthreads();
    float acc = 0.0f;
#pragma unroll
    for (int k = 0; k < 64; k++) acc += in_s[ty][k] * Ws[k * 64 + tx];
    g_Ah[node * 64 + tx] = __float2half_rn(acc);
}

// ---------------- pull aggregation: B[d] = di^2*A[d] + sum w*A[s] -----------
// 16 threads per node, each owns 4 features (8B of the 128B fp16 row).
// fp32 accumulate; no atomics; B written exactly once.
__global__ void k_agg() {
    int t = threadIdx.x;
    int node = blockIdx.x * 16 + (t >> 4);
    int c = t & 15;
    const uint2* __restrict__ a8 = reinterpret_cast<const uint2*>(g_Ah); // 16 uint2/row

#define UNPACK(pk, f0, f1)                                            \
    {   __half2 _h0 = *reinterpret_cast<const __half2*>(&(pk).x);     \
        __half2 _h1 = *reinterpret_cast<const __half2*>(&(pk).y);     \
        f0 = __half22float2(_h0); f1 = __half22float2(_h1); }

    float di = g_dinv[node];
    float ws = di * di;
    uint2 spk = a8[node * 16 + c];
    float2 s0, s1; UNPACK(spk, s0, s1);
    float4 acc = make_float4(ws * s0.x, ws * s0.y, ws * s1.x, ws * s1.y);

    int b = g_row[node];
    int e = g_row[node + 1];
    int i = b;
    for (; i + 3 < e; i += 4) {
        int2 p0 = g_epack[i],     p1 = g_epack[i + 1];
        int2 p2 = g_epack[i + 2], p3 = g_epack[i + 3];
        uint2 q0 = a8[p0.x * 16 + c], q1 = a8[p1.x * 16 + c];
        uint2 q2 = a8[p2.x * 16 + c], q3 = a8[p3.x * 16 + c];
        float w0 = __int_as_float(p0.y), w1 = __int_as_float(p1.y);
        float w2 = __int_as_float(p2.y), w3 = __int_as_float(p3.y);
        float2 a0, a1; UNPACK(q0, a0, a1);
        float2 b0, b1; UNPACK(q1, b0, b1);
        float2 c0, c1; UNPACK(q2, c0, c1);
        float2 d0, d1; UNPACK(q3, d0, d1);
        acc.x += w0 * a0.x + w1 * b0.x + w2 * c0.x + w3 * d0.x;
        acc.y += w0 * a0.y + w1 * b0.y + w2 * c0.y + w3 * d0.y;
        acc.z += w0 * a1.x + w1 * b1.x + w2 * c1.x + w3 * d1.x;
        acc.w += w0 * a1.y + w1 * b1.y + w2 * c1.y + w3 * d1.y;
    }
    for (; i < e; i++) {
        int2 p = g_epack[i];
        uint2 q = a8[p.x * 16 + c];
        float w = __int_as_float(p.y);
        float2 a0, a1; UNPACK(q, a0, a1);
        acc.x += w * a0.x; acc.y += w * a0.y;
        acc.z += w * a1.x; acc.w += w * a1.y;
    }
#undef UNPACK
    reinterpret_cast<float4*>(g_B)[node * 16 + c] = acc;
}

// ---------------- pool: run-length compressed atomics (batch is sorted) -----
__global__ void k_pool(const int* __restrict__ batch, const float* __restrict__ b3) {
    int t = threadIdx.x;
    int j = t & 63;
    int base = (blockIdx.x * 4 + (t >> 6)) * 16;    // 16 consecutive nodes
    float bias = b3[j];
    int gcur = batch[base];
    float acc = 0.0f;
    int cnt = 0;
#pragma unroll
    for (int k = 0; k < 16; k++) {
        int node = base + k;
        int g = batch[node];
        if (g != gcur) {
            atomicAdd(&g_sums[gcur * 64 + j], acc);
            if (j == 0) atomicAdd(&g_cnt[gcur], (float)cnt);
            acc = 0.0f; cnt = 0; gcur = g;
        }
        acc += fmaxf(g_B[node * 64 + j] + bias, 0.0f);
        cnt++;
    }
    atomicAdd(&g_sums[gcur * 64 + j], acc);
    if (j == 0) atomicAdd(&g_cnt[gcur], (float)cnt);
}

// ---------------- MLP head: one block (64 thr) per graph --------------------
__global__ void k_mlp(const float* __restrict__ Wf1, const float* __restrict__ bf1,
                      const float* __restrict__ Wf2, const float* __restrict__ bf2,
                      float* __restrict__ out) {
    __shared__ float p[64];
    __shared__ float hid[64];
    int g = blockIdx.x;
    int tx = threadIdx.x;
    float cnt = fmaxf(g_cnt[g], 1.0f);
    p[tx] = g_sums[g * 64 + tx] / cnt;
    __syncthreads();
    float a = bf1[tx];
#pragma unroll
    for (int k = 0; k < 64; k++) a += p[k] * Wf1[k * 64 + tx];
    hid[tx] = fmaxf(a, 0.0f);
    __syncthreads();
    if (tx < N_CLASSES) {
        float o = bf2[tx];
#pragma unroll
        for (int k = 0; k < 64; k++) o += hid[k] * Wf2[k * N_CLASSES + tx];
        out[g * N_CLASSES + tx] = o;
    }
}

// ---------------- launch ----------------------------------------------------
extern "C" void kernel_launch(void* const* d_in, const int* in_sizes, int n_in,
                              void* d_out, int out_size) {
    const float* x     = (const float*)d_in[0];
    const int*   ei    = (const int*)d_in[1];     // [2, E] int32
    const int*   batch = (const int*)d_in[2];     // [N] int32
    const float* W1  = (const float*)d_in[3];
    const float* b1  = (const float*)d_in[4];
    const float* W2  = (const float*)d_in[5];
    const float* b2  = (const float*)d_in[6];
    const float* W3  = (const float*)d_in[7];
    const float* b3  = (const float*)d_in[8];
    const float* Wf1 = (const float*)d_in[9];
    const float* bf1 = (const float*)d_in[10];
    const float* Wf2 = (const float*)d_in[11];
    const float* bf2 = (const float*)d_in[12];
    float* out = (float*)d_out;

    const int* src = ei;
    const int* dst = ei + N_EDGES;

    const int gridEdge = (N_EDGES + 255) / 256;     // 12500
    const int gridNode = (N_NODES + 255) / 256;     // 782
    const int gridAgg  = N_NODES / 16;              // 12500

    // ---- CSR build (once, reused by all 3 layers) ----
    k_init<<<(N_GRAPHS * HIDDEN + 255) / 256, 256>>>();
    k_deg<<<gridEdge, 256>>>(dst);
    k_scan1<<<N_SBLK, SCAN_BLK>>>();
    k_scan2<<<1, 256>>>();
    k_scan3<<<gridNode, 256>>>();
    k_fill<<<gridEdge, 256>>>(src, dst);

    // ---- layer 1 ----
    k_dense1<<<(N_NODES * 16 + 255) / 256, 256>>>(x, W1);
    k_agg<<<gridAgg, 256>>>();
    // ---- layer 2 (applies b1+relu) ----
    k_dense<<<N_NODES / 8, 512>>>(W2, b1);
    k_agg<<<gridAgg, 256>>>();
    // ---- layer 3 (applies b2+relu) ----
    k_dense<<<N_NODES / 8, 512>>>(W3, b2);
    k_agg<<<gridAgg, 256>>>();

    // ---- pool (applies b3+relu) + head ----
    k_pool<<<N_NODES / 64, 256>>>(batch, b3);
    k_mlp<<<N_GRAPHS, 64>>>(Wf1, bf1, Wf2, bf2, out);
}

// round 14
// speedup vs baseline: 2.2526x; 1.2604x over previous
#include <cuda_runtime.h>
#include <cuda_fp16.h>

#define N_NODES   200000
#define N_EDGES   3200000
#define HIDDEN    64
#define N_GRAPHS  4096
#define N_CLASSES 7

#define SCAN_BLK  1024
#define N_SBLK    ((N_NODES + SCAN_BLK - 1) / SCAN_BLK)   // 196

// ---------------- scratch (static device globals; no runtime allocation) ----
__device__ __align__(16) __half g_Ah[(size_t)N_NODES * HIDDEN]; // fp16 features
__device__ __align__(16) float  g_B[(size_t)N_NODES * HIDDEN];  // fp32 aggregated
__device__ float g_dinv[N_NODES];
__device__ int   g_count[N_NODES];
__device__ int   g_row[N_NODES + 1];
__device__ int   g_cursor[N_NODES];
__device__ int   g_bsum[N_SBLK];
__device__ __align__(8) int2 g_epack[N_EDGES];   // (src, weight bits) by dst
__device__ float g_sums[N_GRAPHS * HIDDEN];
__device__ float g_cnt[N_GRAPHS];

// ---------------- init ------------------------------------------------------
__global__ void k_init() {
    int i = blockIdx.x * blockDim.x + threadIdx.x;
    if (i < N_NODES) g_count[i] = 0;
    if (i < N_GRAPHS * HIDDEN) g_sums[i] = 0.0f;
    if (i < N_GRAPHS) g_cnt[i] = 0.0f;
}

// ---------------- degree histogram over dst ---------------------------------
__global__ void k_deg(const int* __restrict__ dst) {
    int e = blockIdx.x * blockDim.x + threadIdx.x;
    if (e < N_EDGES) atomicAdd(&g_count[dst[e]], 1);
}

// ---------------- prefix scan (3 kernels) -----------------------------------
__global__ void k_scan1() {
    __shared__ int sh[SCAN_BLK];
    int t = threadIdx.x;
    int i = blockIdx.x * SCAN_BLK + t;
    int v = (i < N_NODES) ? g_count[i] : 0;
    sh[t] = v;
    __syncthreads();
    for (int off = 1; off < SCAN_BLK; off <<= 1) {
        int x = (t >= off) ? sh[t - off] : 0;
        __syncthreads();
        sh[t] += x;
        __syncthreads();
    }
    if (i < N_NODES) g_row[i] = sh[t] - v;
    if (t == SCAN_BLK - 1) g_bsum[blockIdx.x] = sh[t];
}

__global__ void k_scan2() {
    __shared__ int sh[256];
    int t = threadIdx.x;
    int v = (t < N_SBLK) ? g_bsum[t] : 0;
    sh[t] = v;
    __syncthreads();
    for (int off = 1; off < 256; off <<= 1) {
        int x = (t >= off) ? sh[t - off] : 0;
        __syncthreads();
        sh[t] += x;
        __syncthreads();
    }
    if (t < N_SBLK) g_bsum[t] = sh[t] - v;
}

__global__ void k_scan3() {
    int i = blockIdx.x * blockDim.x + threadIdx.x;
    if (i >= N_NODES) return;
    int r = g_row[i] + g_bsum[i / SCAN_BLK];
    g_row[i] = r;
    g_cursor[i] = r;
    g_dinv[i] = rsqrtf((float)(g_count[i] + 1));    // +1 self-loop
    if (i == 0) g_row[N_NODES] = N_EDGES;
}

// ---------------- fill CSR --------------------------------------------------
__global__ void k_fill(const int* __restrict__ src, const int* __restrict__ dst) {
    int e = blockIdx.x * blockDim.x + threadIdx.x;
    if (e >= N_EDGES) return;
    int s = src[e];
    int d = dst[e];
    float w = g_dinv[s] * g_dinv[d];
    int pos = atomicAdd(&g_cursor[d], 1);
    g_epack[pos] = make_int2(s, __float_as_int(w));
}

// ---------------- layer 1 dense: x[N,2] @ W1[2,64] -> fp16 A ----------------
__global__ void k_dense1(const float* __restrict__ x, const float* __restrict__ W1) {
    int idx = blockIdx.x * blockDim.x + threadIdx.x;      // N*16 threads
    if (idx >= N_NODES * 16) return;
    int i = idx >> 4;
    int c = idx & 15;
    float x0 = x[2 * i], x1 = x[2 * i + 1];
    float4 wa = *reinterpret_cast<const float4*>(W1 + 4 * c);
    float4 wb = *reinterpret_cast<const float4*>(W1 + 64 + 4 * c);
    __half2 h0 = __floats2half2_rn(x0 * wa.x + x1 * wb.x, x0 * wa.y + x1 * wb.y);
    __half2 h1 = __floats2half2_rn(x0 * wa.z + x1 * wb.z, x0 * wa.w + x1 * wb.w);
    uint2 pk;
    pk.x = *reinterpret_cast<unsigned*>(&h0);
    pk.y = *reinterpret_cast<unsigned*>(&h1);
    reinterpret_cast<uint2*>(g_Ah)[idx] = pk;
}

// ---------------- layers 2/3 dense: relu(B + b_prev) @ W[64,64] -> fp16 A ---
// 256 thr: tx(16 j-groups of 4 outputs) x ty(16 nodes). Per k: 1 broadcast LDS
// + 1 LDS.128 + 4 FFMA -> FFMA-pipe-bound.
__global__ void k_dense(const float* __restrict__ W, const float* __restrict__ bprev) {
    __shared__ float Ws[64 * 64];
    __shared__ float in_s[16][65];
    int t = threadIdx.x;
    int tx = t & 15;
    int ty = t >> 4;
    {
        const float4* W4 = reinterpret_cast<const float4*>(W);
        float4* Ws4 = reinterpret_cast<float4*>(Ws);
#pragma unroll
        for (int i = t; i < 1024; i += 256) Ws4[i] = W4[i];
    }
    int node = blockIdx.x * 16 + ty;
    {
        float4 v = reinterpret_cast<const float4*>(g_B)[node * 16 + tx];
        float4 bb = reinterpret_cast<const float4*>(bprev)[tx];
        in_s[ty][tx * 4 + 0] = fmaxf(v.x + bb.x, 0.0f);
        in_s[ty][tx * 4 + 1] = fmaxf(v.y + bb.y, 0.0f);
        in_s[ty][tx * 4 + 2] = fmaxf(v.z + bb.z, 0.0f);
        in_s[ty][tx * 4 + 3] = fmaxf(v.w + bb.w, 0.0f);
    }
    __syncthreads();
    float a0 = 0.0f, a1 = 0.0f, a2 = 0.0f, a3 = 0.0f;
#pragma unroll
    for (int k = 0; k < 64; k++) {
        float xv = in_s[ty][k];
        float4 w = *reinterpret_cast<const float4*>(&Ws[k * 64 + tx * 4]);
        a0 += xv * w.x; a1 += xv * w.y; a2 += xv * w.z; a3 += xv * w.w;
    }
    __half2 h0 = __floats2half2_rn(a0, a1);
    __half2 h1 = __floats2half2_rn(a2, a3);
    uint2 pk;
    pk.x = *reinterpret_cast<unsigned*>(&h0);
    pk.y = *reinterpret_cast<unsigned*>(&h1);
    reinterpret_cast<uint2*>(g_Ah)[node * 16 + tx] = pk;
}

// ---------------- pull aggregation ------------------------------------------
// 8 lanes per node, each owns 16B (8 halves) of the 128B fp16 row -> LDG.128
// gathers, 0.5 LDG-instr/edge. fp32 accumulate, no atomics, B written once.
__device__ __forceinline__ void agg_edge(float acc[8], uint4 q, float w) {
    float2 u0 = __half22float2(*reinterpret_cast<const __half2*>(&q.x));
    float2 u1 = __half22float2(*reinterpret_cast<const __half2*>(&q.y));
    float2 u2 = __half22float2(*reinterpret_cast<const __half2*>(&q.z));
    float2 u3 = __half22float2(*reinterpret_cast<const __half2*>(&q.w));
    acc[0] += w * u0.x; acc[1] += w * u0.y;
    acc[2] += w * u1.x; acc[3] += w * u1.y;
    acc[4] += w * u2.x; acc[5] += w * u2.y;
    acc[6] += w * u3.x; acc[7] += w * u3.y;
}

__global__ void k_agg() {
    int t = threadIdx.x;
    int node = blockIdx.x * 32 + (t >> 3);          // 32 nodes / 256-thr block
    int c = t & 7;                                  // 8 lanes per node
    const uint4* __restrict__ a16 = reinterpret_cast<const uint4*>(g_Ah);
    float di = g_dinv[node];
    float ws = di * di;
    float acc[8];
    agg_edge(acc, make_uint4(0, 0, 0, 0), 0.0f);    // (no-op pattern避免) -- replaced below
    {
        uint4 sp = a16[node * 8 + c];
        float2 u0 = __half22float2(*reinterpret_cast<const __half2*>(&sp.x));
        float2 u1 = __half22float2(*reinterpret_cast<const __half2*>(&sp.y));
        float2 u2 = __half22float2(*reinterpret_cast<const __half2*>(&sp.z));
        float2 u3 = __half22float2(*reinterpret_cast<const __half2*>(&sp.w));
        acc[0] = ws * u0.x; acc[1] = ws * u0.y;
        acc[2] = ws * u1.x; acc[3] = ws * u1.y;
        acc[4] = ws * u2.x; acc[5] = ws * u2.y;
        acc[6] = ws * u3.x; acc[7] = ws * u3.y;
    }
    int b = g_row[node];
    int e = g_row[node + 1];
    int i = b;
    for (; i + 3 < e; i += 4) {
        int2 p0 = g_epack[i],     p1 = g_epack[i + 1];
        int2 p2 = g_epack[i + 2], p3 = g_epack[i + 3];
        uint4 q0 = a16[p0.x * 8 + c];
        uint4 q1 = a16[p1.x * 8 + c];
        uint4 q2 = a16[p2.x * 8 + c];
        uint4 q3 = a16[p3.x * 8 + c];
        agg_edge(acc, q0, __int_as_float(p0.y));
        agg_edge(acc, q1, __int_as_float(p1.y));
        agg_edge(acc, q2, __int_as_float(p2.y));
        agg_edge(acc, q3, __int_as_float(p3.y));
    }
    for (; i < e; i++) {
        int2 p = g_epack[i];
        uint4 q = a16[p.x * 8 + c];
        agg_edge(acc, q, __int_as_float(p.y));
    }
    float4* B4 = reinterpret_cast<float4*>(g_B);
    B4[node * 16 + c * 2 + 0] = make_float4(acc[0], acc[1], acc[2], acc[3]);
    B4[node * 16 + c * 2 + 1] = make_float4(acc[4], acc[5], acc[6], acc[7]);
}

// ---------------- pool: run-length compressed atomics (batch sorted) --------
__global__ void k_pool(const int* __restrict__ batch, const float* __restrict__ b3) {
    int t = threadIdx.x;
    int j = t & 63;
    int base = (blockIdx.x * 4 + (t >> 6)) * 16;
    float bias = b3[j];
    int gcur = batch[base];
    float acc = 0.0f;
    int cnt = 0;
#pragma unroll
    for (int k = 0; k < 16; k++) {
        int node = base + k;
        int g = batch[node];
        if (g != gcur) {
            atomicAdd(&g_sums[gcur * 64 + j], acc);
            if (j == 0) atomicAdd(&g_cnt[gcur], (float)cnt);
            acc = 0.0f; cnt = 0; gcur = g;
        }
        acc += fmaxf(g_B[node * 64 + j] + bias, 0.0f);
        cnt++;
    }
    atomicAdd(&g_sums[gcur * 64 + j], acc);
    if (j == 0) atomicAdd(&g_cnt[gcur], (float)cnt);
}

// ---------------- MLP head --------------------------------------------------
__global__ void k_mlp(const float* __restrict__ Wf1, const float* __restrict__ bf1,
                      const float* __restrict__ Wf2, const float* __restrict__ bf2,
                      float* __restrict__ out) {
    __shared__ float p[64];
    __shared__ float hid[64];
    int g = blockIdx.x;
    int tx = threadIdx.x;
    float cnt = fmaxf(g_cnt[g], 1.0f);
    p[tx] = g_sums[g * 64 + tx] / cnt;
    __syncthreads();
    float a = bf1[tx];
#pragma unroll
    for (int k = 0; k < 64; k++) a += p[k] * Wf1[k * 64 + tx];
    hid[tx] = fmaxf(a, 0.0f);
    __syncthreads();
    if (tx < N_CLASSES) {
        float o = bf2[tx];
#pragma unroll
        for (int k = 0; k < 64; k++) o += hid[k] * Wf2[k * N_CLASSES + tx];
        out[g * N_CLASSES + tx] = o;
    }
}

// ---------------- launch ----------------------------------------------------
extern "C" void kernel_launch(void* const* d_in, const int* in_sizes, int n_in,
                              void* d_out, int out_size) {
    const float* x     = (const float*)d_in[0];
    const int*   ei    = (const int*)d_in[1];     // [2, E] int32
    const int*   batch = (const int*)d_in[2];     // [N] int32
    const float* W1  = (const float*)d_in[3];
    const float* b1  = (const float*)d_in[4];
    const float* W2  = (const float*)d_in[5];
    const float* b2  = (const float*)d_in[6];
    const float* W3  = (const float*)d_in[7];
    const float* b3  = (const float*)d_in[8];
    const float* Wf1 = (const float*)d_in[9];
    const float* bf1 = (const float*)d_in[10];
    const float* Wf2 = (const float*)d_in[11];
    const float* bf2 = (const float*)d_in[12];
    float* out = (float*)d_out;

    const int* src = ei;
    const int* dst = ei + N_EDGES;

    const int gridEdge = (N_EDGES + 255) / 256;     // 12500
    const int gridNode = (N_NODES + 255) / 256;     // 782
    const int gridAgg  = N_NODES / 32;              // 6250
    const int gridDense = N_NODES / 16;             // 12500

    // ---- CSR build (once, reused by all 3 layers) ----
    k_init<<<(N_GRAPHS * HIDDEN + 255) / 256, 256>>>();
    k_deg<<<gridEdge, 256>>>(dst);
    k_scan1<<<N_SBLK, SCAN_BLK>>>();
    k_scan2<<<1, 256>>>();
    k_scan3<<<gridNode, 256>>>();
    k_fill<<<gridEdge, 256>>>(src, dst);

    // ---- layer 1 ----
    k_dense1<<<(N_NODES * 16 + 255) / 256, 256>>>(x, W1);
    k_agg<<<gridAgg, 256>>>();
    // ---- layer 2 (applies b1+relu) ----
    k_dense<<<gridDense, 256>>>(W2, b1);
    k_agg<<<gridAgg, 256>>>();
    // ---- layer 3 (applies b2+relu) ----
    k_dense<<<gridDense, 256>>>(W3, b2);
    k_agg<<<gridAgg, 256>>>();

    // ---- pool (applies b3+relu) + head ----
    k_pool<<<N_NODES / 64, 256>>>(batch, b3);
    k_mlp<<<N_GRAPHS, 64>>>(Wf1, bf1, Wf2, bf2, out);
}

// round 15
// speedup vs baseline: 3.7202x; 1.6515x over previous
#include <cuda_runtime.h>
#include <cuda_fp16.h>

#define N_NODES   200000
#define N_EDGES   3200000
#define HIDDEN    64
#define N_GRAPHS  4096
#define N_CLASSES 7

#define SCAN_BLK  1024
#define N_SBLK    ((N_NODES + SCAN_BLK - 1) / SCAN_BLK)   // 196

// ---------------- scratch (static device globals; no runtime allocation) ----
__device__ __align__(16) __half g_Ah[(size_t)N_NODES * HIDDEN]; // fp16 features
__device__ __align__(16) float  g_B[(size_t)N_NODES * HIDDEN];  // fp32 aggregated
__device__ float g_dinv[N_NODES];
__device__ int   g_count[N_NODES];
__device__ int   g_row[N_NODES + 1];
__device__ int   g_cursor[N_NODES];
__device__ int   g_bsum[N_SBLK];
__device__ __align__(8) int2 g_epack[N_EDGES];   // (src, weight bits) by dst
__device__ float g_sums[N_GRAPHS * HIDDEN];
__device__ float g_cnt[N_GRAPHS];

__device__ __forceinline__ unsigned smem_u32(const void* p) {
    unsigned a;
    asm("{ .reg .u64 t; cvta.to.shared.u64 t, %1; cvt.u32.u64 %0, t; }"
        : "=r"(a) : "l"(p));
    return a;
}

// ---------------- init ------------------------------------------------------
__global__ void k_init() {
    int i = blockIdx.x * blockDim.x + threadIdx.x;
    if (i < N_NODES) g_count[i] = 0;
    if (i < N_GRAPHS * HIDDEN) g_sums[i] = 0.0f;
    if (i < N_GRAPHS) g_cnt[i] = 0.0f;
}

// ---------------- degree histogram over dst ---------------------------------
__global__ void k_deg(const int* __restrict__ dst) {
    int e = blockIdx.x * blockDim.x + threadIdx.x;
    if (e < N_EDGES) atomicAdd(&g_count[dst[e]], 1);
}

// ---------------- prefix scan (3 kernels) -----------------------------------
__global__ void k_scan1() {
    __shared__ int sh[SCAN_BLK];
    int t = threadIdx.x;
    int i = blockIdx.x * SCAN_BLK + t;
    int v = (i < N_NODES) ? g_count[i] : 0;
    sh[t] = v;
    __syncthreads();
    for (int off = 1; off < SCAN_BLK; off <<= 1) {
        int x = (t >= off) ? sh[t - off] : 0;
        __syncthreads();
        sh[t] += x;
        __syncthreads();
    }
    if (i < N_NODES) g_row[i] = sh[t] - v;
    if (t == SCAN_BLK - 1) g_bsum[blockIdx.x] = sh[t];
}

__global__ void k_scan2() {
    __shared__ int sh[256];
    int t = threadIdx.x;
    int v = (t < N_SBLK) ? g_bsum[t] : 0;
    sh[t] = v;
    __syncthreads();
    for (int off = 1; off < 256; off <<= 1) {
        int x = (t >= off) ? sh[t - off] : 0;
        __syncthreads();
        sh[t] += x;
        __syncthreads();
    }
    if (t < N_SBLK) g_bsum[t] = sh[t] - v;
}

__global__ void k_scan3() {
    int i = blockIdx.x * blockDim.x + threadIdx.x;
    if (i >= N_NODES) return;
    int r = g_row[i] + g_bsum[i / SCAN_BLK];
    g_row[i] = r;
    g_cursor[i] = r;
    g_dinv[i] = rsqrtf((float)(g_count[i] + 1));    // +1 self-loop
    if (i == 0) g_row[N_NODES] = N_EDGES;
}

// ---------------- fill CSR --------------------------------------------------
__global__ void k_fill(const int* __restrict__ src, const int* __restrict__ dst) {
    int e = blockIdx.x * blockDim.x + threadIdx.x;
    if (e >= N_EDGES) return;
    int s = src[e];
    int d = dst[e];
    float w = g_dinv[s] * g_dinv[d];
    int pos = atomicAdd(&g_cursor[d], 1);
    g_epack[pos] = make_int2(s, __float_as_int(w));
}

// ---------------- layer 1 dense: x[N,2] @ W1[2,64] -> fp16 A (8 outs/thr) ---
__global__ void k_dense1(const float* __restrict__ x, const float* __restrict__ W1) {
    int idx = blockIdx.x * blockDim.x + threadIdx.x;      // N*8 threads
    if (idx >= N_NODES * 8) return;
    int i = idx >> 3;
    int c = idx & 7;                                      // 8-feature group
    float x0 = x[2 * i], x1 = x[2 * i + 1];
    float4 wa0 = *reinterpret_cast<const float4*>(W1 + 8 * c);
    float4 wa1 = *reinterpret_cast<const float4*>(W1 + 8 * c + 4);
    float4 wb0 = *reinterpret_cast<const float4*>(W1 + 64 + 8 * c);
    float4 wb1 = *reinterpret_cast<const float4*>(W1 + 64 + 8 * c + 4);
    __half2 h0 = __floats2half2_rn(x0 * wa0.x + x1 * wb0.x, x0 * wa0.y + x1 * wb0.y);
    __half2 h1 = __floats2half2_rn(x0 * wa0.z + x1 * wb0.z, x0 * wa0.w + x1 * wb0.w);
    __half2 h2 = __floats2half2_rn(x0 * wa1.x + x1 * wb1.x, x0 * wa1.y + x1 * wb1.y);
    __half2 h3 = __floats2half2_rn(x0 * wa1.z + x1 * wb1.z, x0 * wa1.w + x1 * wb1.w);
    uint4 pk;
    pk.x = *reinterpret_cast<unsigned*>(&h0);
    pk.y = *reinterpret_cast<unsigned*>(&h1);
    pk.z = *reinterpret_cast<unsigned*>(&h2);
    pk.w = *reinterpret_cast<unsigned*>(&h3);
    reinterpret_cast<uint4*>(g_Ah)[idx] = pk;
}

// ---------------- layers 2/3 dense via tensor cores -------------------------
// relu(B + b_prev) @ W[64,64] -> fp16 A.  Block: 128 thr = 4 warps = 64 nodes,
// each warp computes a 16x64 output tile with mma.sync.m16n8k16 (f16 in, f32 acc).
#define DPAD 72   // smem row stride in halves (8-half pad kills ldmatrix conflicts)
__global__ void k_dense(const float* __restrict__ W, const float* __restrict__ bprev) {
    __shared__ __half Wh[64 * DPAD];
    __shared__ __half Ih[64 * DPAD];
    int t = threadIdx.x;
    int lane = t & 31;
    int warp = t >> 5;
    int nodeBase = blockIdx.x * 64;

    // W[64x64] fp32 -> fp16 smem (row-major k x n)
    for (int i = t; i < 4096; i += 128)
        Wh[(i >> 6) * DPAD + (i & 63)] = __float2half_rn(W[i]);

    // inputs: relu(B + bias) -> fp16 smem (row = local node)
    for (int i = t; i < 1024; i += 128) {                 // 1024 float4s
        int node = i >> 4;
        int jj = i & 15;
        float4 v = reinterpret_cast<const float4*>(g_B)[(nodeBase + node) * 16 + jj];
        float4 bb = reinterpret_cast<const float4*>(bprev)[jj];
        __half2 p0 = __floats2half2_rn(fmaxf(v.x + bb.x, 0.0f), fmaxf(v.y + bb.y, 0.0f));
        __half2 p1 = __floats2half2_rn(fmaxf(v.z + bb.z, 0.0f), fmaxf(v.w + bb.w, 0.0f));
        __half2* dstp = reinterpret_cast<__half2*>(&Ih[node * DPAD + jj * 4]);
        dstp[0] = p0;
        dstp[1] = p1;
    }
    __syncthreads();

    // A fragments: 4 k-tiles of 16x16 from Ih
    unsigned baseI = smem_u32(Ih);
    unsigned baseW = smem_u32(Wh);
    int warpM = warp * 16;
    unsigned a[4][4];
#pragma unroll
    for (int kt = 0; kt < 4; kt++) {
        unsigned addr = baseI + (((warpM + (lane & 15)) * DPAD) + kt * 16 + ((lane >> 4) << 3)) * 2;
        asm volatile("ldmatrix.sync.aligned.m8n8.x4.shared.b16 {%0,%1,%2,%3}, [%4];"
                     : "=r"(a[kt][0]), "=r"(a[kt][1]), "=r"(a[kt][2]), "=r"(a[kt][3])
                     : "r"(addr));
    }

    int r0 = lane >> 2;                 // output row within tile
    int cc = (lane & 3) * 2;            // output col pair within n-tile
#pragma unroll
    for (int nt = 0; nt < 8; nt++) {
        float c0 = 0.f, c1 = 0.f, c2 = 0.f, c3 = 0.f;
#pragma unroll
        for (int kt = 0; kt < 4; kt++) {
            unsigned b0, b1;
            unsigned addr = baseW + ((kt * 16 + (lane & 15)) * DPAD + nt * 8) * 2;
            asm volatile("ldmatrix.sync.aligned.m8n8.x2.trans.shared.b16 {%0,%1}, [%2];"
                         : "=r"(b0), "=r"(b1) : "r"(addr));
            asm volatile(
                "mma.sync.aligned.m16n8k16.row.col.f32.f16.f16.f32 "
                "{%0,%1,%2,%3}, {%4,%5,%6,%7}, {%8,%9}, {%0,%1,%2,%3};"
                : "+f"(c0), "+f"(c1), "+f"(c2), "+f"(c3)
                : "r"(a[kt][0]), "r"(a[kt][1]), "r"(a[kt][2]), "r"(a[kt][3]),
                  "r"(b0), "r"(b1));
        }
        int col = nt * 8 + cc;
        __half2 h01 = __floats2half2_rn(c0, c1);
        __half2 h23 = __floats2half2_rn(c2, c3);
        *reinterpret_cast<__half2*>(&g_Ah[(size_t)(nodeBase + warpM + r0) * 64 + col]) = h01;
        *reinterpret_cast<__half2*>(&g_Ah[(size_t)(nodeBase + warpM + r0 + 8) * 64 + col]) = h23;
    }
}

// ---------------- pull aggregation ------------------------------------------
// 8 lanes per node, each owns 16B (8 halves) of the 128B fp16 row -> LDG.128
// gathers. fp32 accumulate, no atomics, B written once.
__device__ __forceinline__ void agg_edge(float acc[8], uint4 q, float w) {
    float2 u0 = __half22float2(*reinterpret_cast<const __half2*>(&q.x));
    float2 u1 = __half22float2(*reinterpret_cast<const __half2*>(&q.y));
    float2 u2 = __half22float2(*reinterpret_cast<const __half2*>(&q.z));
    float2 u3 = __half22float2(*reinterpret_cast<const __half2*>(&q.w));
    acc[0] += w * u0.x; acc[1] += w * u0.y;
    acc[2] += w * u1.x; acc[3] += w * u1.y;
    acc[4] += w * u2.x; acc[5] += w * u2.y;
    acc[6] += w * u3.x; acc[7] += w * u3.y;
}

__global__ void k_agg() {
    int t = threadIdx.x;
    int node = blockIdx.x * 32 + (t >> 3);          // 32 nodes / 256-thr block
    int c = t & 7;                                  // 8 lanes per node
    const uint4* __restrict__ a16 = reinterpret_cast<const uint4*>(g_Ah);
    float di = g_dinv[node];
    float ws = di * di;
    float acc[8];
    {
        uint4 sp = a16[node * 8 + c];
        float2 u0 = __half22float2(*reinterpret_cast<const __half2*>(&sp.x));
        float2 u1 = __half22float2(*reinterpret_cast<const __half2*>(&sp.y));
        float2 u2 = __half22float2(*reinterpret_cast<const __half2*>(&sp.z));
        float2 u3 = __half22float2(*reinterpret_cast<const __half2*>(&sp.w));
        acc[0] = ws * u0.x; acc[1] = ws * u0.y;
        acc[2] = ws * u1.x; acc[3] = ws * u1.y;
        acc[4] = ws * u2.x; acc[5] = ws * u2.y;
        acc[6] = ws * u3.x; acc[7] = ws * u3.y;
    }
    int b = g_row[node];
    int e = g_row[node + 1];
    int i = b;
    for (; i + 3 < e; i += 4) {
        int2 p0 = g_epack[i],     p1 = g_epack[i + 1];
        int2 p2 = g_epack[i + 2], p3 = g_epack[i + 3];
        uint4 q0 = a16[p0.x * 8 + c];
        uint4 q1 = a16[p1.x * 8 + c];
        uint4 q2 = a16[p2.x * 8 + c];
        uint4 q3 = a16[p3.x * 8 + c];
        agg_edge(acc, q0, __int_as_float(p0.y));
        agg_edge(acc, q1, __int_as_float(p1.y));
        agg_edge(acc, q2, __int_as_float(p2.y));
        agg_edge(acc, q3, __int_as_float(p3.y));
    }
    for (; i < e; i++) {
        int2 p = g_epack[i];
        uint4 q = a16[p.x * 8 + c];
        agg_edge(acc, q, __int_as_float(p.y));
    }
    float4* B4 = reinterpret_cast<float4*>(g_B);
    B4[node * 16 + c * 2 + 0] = make_float4(acc[0], acc[1], acc[2], acc[3]);
    B4[node * 16 + c * 2 + 1] = make_float4(acc[4], acc[5], acc[6], acc[7]);
}

// ---------------- pool: run-length compressed atomics (batch sorted) --------
__global__ void k_pool(const int* __restrict__ batch, const float* __restrict__ b3) {
    int t = threadIdx.x;
    int j = t & 63;
    int base = (blockIdx.x * 4 + (t >> 6)) * 16;
    float bias = b3[j];
    int gcur = batch[base];
    float acc = 0.0f;
    int cnt = 0;
#pragma unroll
    for (int k = 0; k < 16; k++) {
        int node = base + k;
        int g = batch[node];
        if (g != gcur) {
            atomicAdd(&g_sums[gcur * 64 + j], acc);
            if (j == 0) atomicAdd(&g_cnt[gcur], (float)cnt);
            acc = 0.0f; cnt = 0; gcur = g;
        }
        acc += fmaxf(g_B[node * 64 + j] + bias, 0.0f);
        cnt++;
    }
    atomicAdd(&g_sums[gcur * 64 + j], acc);
    if (j == 0) atomicAdd(&g_cnt[gcur], (float)cnt);
}

// ---------------- MLP head --------------------------------------------------
__global__ void k_mlp(const float* __restrict__ Wf1, const float* __restrict__ bf1,
                      const float* __restrict__ Wf2, const float* __restrict__ bf2,
                      float* __restrict__ out) {
    __shared__ float p[64];
    __shared__ float hid[64];
    int g = blockIdx.x;
    int tx = threadIdx.x;
    float cnt = fmaxf(g_cnt[g], 1.0f);
    p[tx] = g_sums[g * 64 + tx] / cnt;
    __syncthreads();
    float a = bf1[tx];
#pragma unroll
    for (int k = 0; k < 64; k++) a += p[k] * Wf1[k * 64 + tx];
    hid[tx] = fmaxf(a, 0.0f);
    __syncthreads();
    if (tx < N_CLASSES) {
        float o = bf2[tx];
#pragma unroll
        for (int k = 0; k < 64; k++) o += hid[k] * Wf2[k * N_CLASSES + tx];
        out[g * N_CLASSES + tx] = o;
    }
}

// ---------------- launch ----------------------------------------------------
extern "C" void kernel_launch(void* const* d_in, const int* in_sizes, int n_in,
                              void* d_out, int out_size) {
    const float* x     = (const float*)d_in[0];
    const int*   ei    = (const int*)d_in[1];     // [2, E] int32
    const int*   batch = (const int*)d_in[2];     // [N] int32
    const float* W1  = (const float*)d_in[3];
    const float* b1  = (const float*)d_in[4];
    const float* W2  = (const float*)d_in[5];
    const float* b2  = (const float*)d_in[6];
    const float* W3  = (const float*)d_in[7];
    const float* b3  = (const float*)d_in[8];
    const float* Wf1 = (const float*)d_in[9];
    const float* bf1 = (const float*)d_in[10];
    const float* Wf2 = (const float*)d_in[11];
    const float* bf2 = (const float*)d_in[12];
    float* out = (float*)d_out;

    const int* src = ei;
    const int* dst = ei + N_EDGES;

    const int gridEdge = (N_EDGES + 255) / 256;     // 12500
    const int gridNode = (N_NODES + 255) / 256;     // 782
    const int gridAgg  = N_NODES / 32;              // 6250
    const int gridDense = N_NODES / 64;             // 3125

    // ---- CSR build (once, reused by all 3 layers) ----
    k_init<<<(N_GRAPHS * HIDDEN + 255) / 256, 256>>>();
    k_deg<<<gridEdge, 256>>>(dst);
    k_scan1<<<N_SBLK, SCAN_BLK>>>();
    k_scan2<<<1, 256>>>();
    k_scan3<<<gridNode, 256>>>();
    k_fill<<<gridEdge, 256>>>(src, dst);

    // ---- layer 1 ----
    k_dense1<<<(N_NODES * 8 + 255) / 256, 256>>>(x, W1);
    k_agg<<<gridAgg, 256>>>();
    // ---- layer 2 (applies b1+relu) ----
    k_dense<<<gridDense, 128>>>(W2, b1);
    k_agg<<<gridAgg, 256>>>();
    // ---- layer 3 (applies b2+relu) ----
    k_dense<<<gridDense, 128>>>(W3, b2);
    k_agg<<<gridAgg, 256>>>();

    // ---- pool (applies b3+relu) + head ----
    k_pool<<<N_NODES / 64, 256>>>(batch, b3);
    k_mlp<<<N_GRAPHS, 64>>>(Wf1, bf1, Wf2, bf2, out);
}